// round 3
// baseline (speedup 1.0000x reference)
#include <cuda_runtime.h>
#include <cstdint>
#include <cstddef>

// Problem constants (fixed by the reference)
#define NTT    1024
#define NGRID  2048
#define HID    128
#define MAXD   8
#define TROWS  (NTT - MAXD)          // 1016 computed time rows
#define NTILES (TROWS * (NGRID/128)) // 16256 tiles of 128 g-rows

// SMEM padded strides (in floats) — chosen for conflict-free mma fragment LDS:
// A stride 132 -> bank = (4*row + col) mod 32 distinct across a fragment load
// B stride 136 -> bank = (8*krow + ncol) mod 32 distinct
#define A_STRIDE 132
#define W_STRIDE 136
#define SMEM_FLOATS (2*128*W_STRIDE + 128*A_STRIDE + 4*128)   // W1,W2,A,b1,b2,wout,yts
#define SMEM_BYTES  (SMEM_FLOATS * 4)                          // 208,896 B

// Device-global scratch (allocation-free rule: __device__ arrays)
__device__ float g_W1[128*128];   // [k][h]  k = (d-1)*16 + c   (conv-folded W_in, tf32)
__device__ float g_W2[128*128];   // [k][h]  = W_ih[h][k]       (tf32)
__device__ float g_b1[128];
__device__ float g_b2[128];       // b_ih + b_hh
__device__ float g_wout[128];
__device__ float g_bout[1];

__device__ __forceinline__ uint32_t f2tf32(float f) {
    uint32_t u;
    asm("cvt.rna.tf32.f32 %0, %1;" : "=r"(u) : "f"(f));
    return u;
}

__device__ __forceinline__ void mma_tf32(float d[4],
                                         uint32_t a0, uint32_t a1, uint32_t a2, uint32_t a3,
                                         uint32_t b0, uint32_t b1) {
    asm volatile(
        "mma.sync.aligned.m16n8k8.row.col.f32.tf32.tf32.f32 "
        "{%0,%1,%2,%3}, {%4,%5,%6,%7}, {%8,%9}, {%0,%1,%2,%3};"
        : "+f"(d[0]), "+f"(d[1]), "+f"(d[2]), "+f"(d[3])
        : "r"(a0), "r"(a1), "r"(a2), "r"(a3), "r"(b0), "r"(b1));
}

// ---------------------------------------------------------------------------
// Prep: fold W_in (128x144, duplicate offset -1) into conv weights Wc[k=128][h],
// transpose W_ih, combine biases. Converts weights to tf32 once.
// feat layout in reference: fx block j*15+c for offsets o_j = [-1,-8,...,-1],
// fy block 135+j. Grouped by delay d (offset -d): j = 9-d, plus j=0 when d==1.
// ---------------------------------------------------------------------------
__global__ void prep_kernel(const float* __restrict__ W_in, const float* __restrict__ b_in,
                            const float* __restrict__ W_ih, const float* __restrict__ b_ih,
                            const float* __restrict__ b_hh, const float* __restrict__ W_out,
                            const float* __restrict__ b_out) {
    int idx = blockIdx.x * blockDim.x + threadIdx.x;
    if (idx < 128*128) {
        int k = idx >> 7, h = idx & 127;
        int d = (k >> 4) + 1;   // delay 1..8
        int c = k & 15;         // channel 0..15 (15 == yf channel)
        int j = 9 - d;          // 1..8
        float v;
        if (c < 15) {
            v = W_in[h*144 + j*15 + c];
            if (d == 1) v += W_in[h*144 + c];          // duplicate offset -1 (j=0)
        } else {
            v = W_in[h*144 + 135 + j];
            if (d == 1) v += W_in[h*144 + 135];
        }
        g_W1[k*128 + h] = __uint_as_float(f2tf32(v));
        g_W2[k*128 + h] = __uint_as_float(f2tf32(W_ih[h*128 + k]));
    }
    if (idx < 128) {
        g_b1[idx]   = b_in[idx];
        g_b2[idx]   = b_ih[idx] + b_hh[idx];
        g_wout[idx] = W_out[idx];
    }
    if (idx == 0) g_bout[0] = b_out[0];
}

// First MAXD output rows are a passthrough of x[t, g, 15]
__global__ void head_kernel(const float* __restrict__ x, float* __restrict__ out) {
    int idx = blockIdx.x * blockDim.x + threadIdx.x;
    if (idx < MAXD * NGRID) out[idx] = x[(size_t)idx * 16 + 15];
}

// ---------------------------------------------------------------------------
// One 128x128x128 tf32 GEMM tile: D += A[128][128] * B[128][128]^T-ish
// A: [row][k] stride A_STRIDE.  B: [k][n] stride W_STRIDE.
// Warp layout: 8 warps = 2 row-halves (64 rows) x 4 col-groups (32 cols).
// ---------------------------------------------------------------------------
__device__ __forceinline__ void gemm_tile(const float* __restrict__ Asrc,
                                          const float* __restrict__ Bsrc,
                                          float acc[4][4][4],
                                          int mb, int nb, int gid, int cq) {
    #pragma unroll
    for (int ks = 0; ks < 16; ks++) {
        const int kA = ks * 8;
        uint32_t b0[4], b1[4];
        const float* Bk = Bsrc + (kA + cq) * W_STRIDE + nb + gid;
        #pragma unroll
        for (int nt = 0; nt < 4; nt++) {
            b0[nt] = __float_as_uint(Bk[nt*8]);
            b1[nt] = __float_as_uint(Bk[4*W_STRIDE + nt*8]);
        }
        #pragma unroll
        for (int mt = 0; mt < 4; mt++) {
            const float* Ar = Asrc + (mb + mt*16 + gid) * A_STRIDE + kA + cq;
            uint32_t a0 = __float_as_uint(Ar[0]);
            uint32_t a1 = __float_as_uint(Ar[8*A_STRIDE]);
            uint32_t a2 = __float_as_uint(Ar[4]);
            uint32_t a3 = __float_as_uint(Ar[8*A_STRIDE + 4]);
            #pragma unroll
            for (int nt = 0; nt < 4; nt++)
                mma_tf32(acc[mt][nt], a0, a1, a2, a3, b0[nt], b1[nt]);
        }
    }
}

// ---------------------------------------------------------------------------
// Persistent main kernel. 1 CTA/SM, 256 threads. Weights resident in SMEM.
// Tile = (one t, 128 consecutive g). Feature tile built from 8 contiguous
// 8KB slabs of x (delays d=1..8). Both GEMMs tf32 mma.sync; GEMM3 fused
// into epilogue2 via shfl + shared atomics.
// ---------------------------------------------------------------------------
__global__ __launch_bounds__(256, 1)
void narx_main(const float* __restrict__ x, float* __restrict__ out) {
    extern __shared__ float sm[];
    float* W1s   = sm;                       // [128][W_STRIDE]
    float* W2s   = W1s + 128*W_STRIDE;       // [128][W_STRIDE]
    float* As    = W2s + 128*W_STRIDE;       // [128][A_STRIDE]  feat / h_in tile
    float* b1s   = As + 128*A_STRIDE;
    float* b2s   = b1s + 128;
    float* wouts = b2s + 128;
    float* yts   = wouts + 128;

    const int tid  = threadIdx.x;
    const int warp = tid >> 5;
    const int lane = tid & 31;
    const int gid  = lane >> 2;   // 0..7
    const int cq   = lane & 3;    // 0..3
    const int mb   = (warp >> 2) * 64;   // row base (0 or 64)
    const int nb   = (warp & 3) * 32;    // col base (0,32,64,96)

    // Load weights once per CTA (persistent)
    for (int i = tid; i < 128*128; i += 256) {
        int k = i >> 7, h = i & 127;
        W1s[k*W_STRIDE + h] = g_W1[i];
        W2s[k*W_STRIDE + h] = g_W2[i];
    }
    if (tid < 128) { b1s[tid] = g_b1[tid]; b2s[tid] = g_b2[tid]; wouts[tid] = g_wout[tid]; }
    __syncthreads();

    const float bout = g_bout[0];

    for (int tile = blockIdx.x; tile < NTILES; tile += gridDim.x) {
        const int t  = MAXD + (tile >> 4);
        const int g0 = (tile & 15) * 128;

        if (tid < 128) yts[tid] = 0.f;

        // Build feature tile: col block d1 = d-1 holds x[t-1-d1, g0:g0+128, 0:16]
        #pragma unroll 4
        for (int i = tid; i < 4096; i += 256) {      // 4096 float4 = 64KB
            int d1 = i >> 9;                          // 0..7 (512 float4 per slab)
            int r  = i & 511;
            const float4 v = *(const float4*)(
                x + (((size_t)(t - 1 - d1)) * NGRID + g0) * 16 + (size_t)r * 4);
            int e = r * 4;
            int g = e >> 4;
            int c = e & 15;
            float4 w;
            w.x = __uint_as_float(f2tf32(v.x));
            w.y = __uint_as_float(f2tf32(v.y));
            w.z = __uint_as_float(f2tf32(v.z));
            w.w = __uint_as_float(f2tf32(v.w));
            *(float4*)(As + g*A_STRIDE + d1*16 + c) = w;
        }
        __syncthreads();   // feat ready, yts zeroed

        // ---- GEMM1: h_pre_in = feat @ Wc^T ----
        float acc[4][4][4];
        #pragma unroll
        for (int mt = 0; mt < 4; mt++)
            #pragma unroll
            for (int nt = 0; nt < 4; nt++)
                #pragma unroll
                for (int q = 0; q < 4; q++) acc[mt][nt][q] = 0.f;

        gemm_tile(As, W1s, acc, mb, nb, gid, cq);
        __syncthreads();   // all feat reads done before overwrite

        // Epilogue1: relu(.+b_in) -> tf32, write h_in back into As
        #pragma unroll
        for (int mt = 0; mt < 4; mt++) {
            int r = mb + mt*16 + gid;
            #pragma unroll
            for (int nt = 0; nt < 4; nt++) {
                int col = nb + nt*8 + 2*cq;
                float bb0 = b1s[col], bb1 = b1s[col+1];
                float2 v0, v1;
                v0.x = __uint_as_float(f2tf32(fmaxf(acc[mt][nt][0] + bb0, 0.f)));
                v0.y = __uint_as_float(f2tf32(fmaxf(acc[mt][nt][1] + bb1, 0.f)));
                v1.x = __uint_as_float(f2tf32(fmaxf(acc[mt][nt][2] + bb0, 0.f)));
                v1.y = __uint_as_float(f2tf32(fmaxf(acc[mt][nt][3] + bb1, 0.f)));
                *(float2*)(As + (size_t)r*A_STRIDE + col)     = v0;
                *(float2*)(As + (size_t)(r+8)*A_STRIDE + col) = v1;
            }
        }
        __syncthreads();   // h_in tile ready

        // ---- GEMM2: h_pre = h_in @ W_ih^T ----
        #pragma unroll
        for (int mt = 0; mt < 4; mt++)
            #pragma unroll
            for (int nt = 0; nt < 4; nt++)
                #pragma unroll
                for (int q = 0; q < 4; q++) acc[mt][nt][q] = 0.f;

        gemm_tile(As, W2s, acc, mb, nb, gid, cq);

        // Epilogue2: tanh(.+b2), fused GEMM3 dot with W_out, reduce
        #pragma unroll
        for (int mt = 0; mt < 4; mt++) {
            float p0 = 0.f, p1 = 0.f;
            #pragma unroll
            for (int nt = 0; nt < 4; nt++) {
                int col = nb + nt*8 + 2*cq;
                float w0 = wouts[col], w1 = wouts[col+1];
                float bb0 = b2s[col], bb1 = b2s[col+1];
                p0 += tanhf(acc[mt][nt][0] + bb0) * w0 + tanhf(acc[mt][nt][1] + bb1) * w1;
                p1 += tanhf(acc[mt][nt][2] + bb0) * w0 + tanhf(acc[mt][nt][3] + bb1) * w1;
            }
            p0 += __shfl_xor_sync(0xffffffffu, p0, 1);
            p0 += __shfl_xor_sync(0xffffffffu, p0, 2);
            p1 += __shfl_xor_sync(0xffffffffu, p1, 1);
            p1 += __shfl_xor_sync(0xffffffffu, p1, 2);
            if (cq == 0) {
                int r = mb + mt*16 + gid;
                atomicAdd(&yts[r],     p0);
                atomicAdd(&yts[r + 8], p1);
            }
        }
        __syncthreads();   // atomics done; also fences As reads vs next-tile writes

        if (tid < 128)
            out[(size_t)t * NGRID + g0 + tid] = yts[tid] + bout;
        // no extra sync needed: yts[tid] next zeroed by the same thread,
        // and As writes of the next tile are ordered by the sync above.
    }
}

extern "C" void kernel_launch(void* const* d_in, const int* in_sizes, int n_in,
                              void* d_out, int out_size) {
    const float* x     = (const float*)d_in[0];
    const float* W_in  = (const float*)d_in[1];
    const float* b_in  = (const float*)d_in[2];
    const float* W_ih  = (const float*)d_in[3];
    const float* b_ih  = (const float*)d_in[4];
    /* d_in[5] = W_hh — dead in the reference (only b_hh is used) */
    const float* b_hh  = (const float*)d_in[6];
    const float* W_out = (const float*)d_in[7];
    const float* b_out = (const float*)d_in[8];
    float* out = (float*)d_out;

    // Idempotent, non-stream host config (legal under capture; no allocation)
    cudaFuncSetAttribute(narx_main, cudaFuncAttributeMaxDynamicSharedMemorySize, SMEM_BYTES);
    int dev = 0, sms = 0;
    cudaGetDevice(&dev);
    cudaDeviceGetAttribute(&sms, cudaDevAttrMultiProcessorCount, dev);
    if (sms <= 0) sms = 148;

    prep_kernel<<<64, 256>>>(W_in, b_in, W_ih, b_ih, b_hh, W_out, b_out);
    head_kernel<<<(MAXD*NGRID + 255)/256, 256>>>(x, out);
    narx_main<<<sms, 256, SMEM_BYTES>>>(x, out);
}

// round 4
// speedup vs baseline: 1.0791x; 1.0791x over previous
#include <cuda_runtime.h>
#include <cstdint>
#include <cstddef>

// Problem constants (fixed by the reference)
#define NTT    1024
#define NGRID  2048
#define HID    128
#define MAXD   8
#define TROWS  (NTT - MAXD)          // 1016 computed time rows
#define NTILES (TROWS * (NGRID/128)) // 16256 tiles of 128 g-rows

// SMEM padded strides (in floats) — conflict-free mma fragment LDS:
// A stride 132 -> bank = (4*row + col) mod 32 distinct across a fragment load
// B stride 136 -> bank = (8*krow + ncol) mod 32 distinct
#define A_STRIDE 132
#define W_STRIDE 136
#define SMEM_FLOATS (2*128*W_STRIDE + 128*A_STRIDE + 4*128)   // W1,W2,A,b1,b2,wout,yts
#define SMEM_BYTES  (SMEM_FLOATS * 4)                          // 208,896 B

// Device-global scratch (allocation-free rule: __device__ arrays)
__device__ float g_W1[128*128];   // [k][h]  k = (d-1)*16 + c   (conv-folded W_in, tf32)
__device__ float g_W2[128*128];   // [k][h]  = W_ih[h][k]       (tf32)
__device__ float g_b1[128];
__device__ float g_b2[128];       // b_ih + b_hh
__device__ float g_wout[128];
__device__ float g_bout[1];

__device__ __forceinline__ uint32_t f2tf32(float f) {
    uint32_t u;
    asm("cvt.rna.tf32.f32 %0, %1;" : "=r"(u) : "f"(f));
    return u;
}

// tanh(x) = 1 - 2/(exp(2x)+1), built from MUFU ex2 + MUFU rcp (~1e-7 rel err,
// vs the ~40-instruction software tanhf the compiler emits without fast-math).
__device__ __forceinline__ float fast_tanh(float x) {
    float e;
    asm("ex2.approx.f32 %0, %1;" : "=f"(e) : "f"(x * 2.885390081777927f)); // 2*log2(e)
    float r;
    asm("rcp.approx.f32 %0, %1;" : "=f"(r) : "f"(e + 1.0f));
    return fmaf(-2.0f, r, 1.0f);   // x>>0 -> 1, x<<0 -> -1, x=0 -> 0
}

__device__ __forceinline__ void mma_tf32(float d[4],
                                         uint32_t a0, uint32_t a1, uint32_t a2, uint32_t a3,
                                         uint32_t b0, uint32_t b1) {
    asm volatile(
        "mma.sync.aligned.m16n8k8.row.col.f32.tf32.tf32.f32 "
        "{%0,%1,%2,%3}, {%4,%5,%6,%7}, {%8,%9}, {%0,%1,%2,%3};"
        : "+f"(d[0]), "+f"(d[1]), "+f"(d[2]), "+f"(d[3])
        : "r"(a0), "r"(a1), "r"(a2), "r"(a3), "r"(b0), "r"(b1));
}

// ---------------------------------------------------------------------------
// Prep: fold W_in (128x144, duplicate offset -1) into conv weights Wc[k=128][h],
// transpose W_ih, combine biases. Converts weights to tf32 once.
// ---------------------------------------------------------------------------
__global__ void prep_kernel(const float* __restrict__ W_in, const float* __restrict__ b_in,
                            const float* __restrict__ W_ih, const float* __restrict__ b_ih,
                            const float* __restrict__ b_hh, const float* __restrict__ W_out,
                            const float* __restrict__ b_out) {
    int idx = blockIdx.x * blockDim.x + threadIdx.x;
    if (idx < 128*128) {
        int k = idx >> 7, h = idx & 127;
        int d = (k >> 4) + 1;   // delay 1..8
        int c = k & 15;         // channel 0..15 (15 == yf channel)
        int j = 9 - d;          // 1..8
        float v;
        if (c < 15) {
            v = W_in[h*144 + j*15 + c];
            if (d == 1) v += W_in[h*144 + c];          // duplicate offset -1 (j=0)
        } else {
            v = W_in[h*144 + 135 + j];
            if (d == 1) v += W_in[h*144 + 135];
        }
        g_W1[k*128 + h] = __uint_as_float(f2tf32(v));
        g_W2[k*128 + h] = __uint_as_float(f2tf32(W_ih[h*128 + k]));
    }
    if (idx < 128) {
        g_b1[idx]   = b_in[idx];
        g_b2[idx]   = b_ih[idx] + b_hh[idx];
        g_wout[idx] = W_out[idx];
    }
    if (idx == 0) g_bout[0] = b_out[0];
}

// First MAXD output rows are a passthrough of x[t, g, 15]
__global__ void head_kernel(const float* __restrict__ x, float* __restrict__ out) {
    int idx = blockIdx.x * blockDim.x + threadIdx.x;
    if (idx < MAXD * NGRID) out[idx] = x[(size_t)idx * 16 + 15];
}

// ---------------------------------------------------------------------------
// One 128x128x128 tf32 GEMM tile.
// A: [row][k] stride A_STRIDE.  B: [k][n] stride W_STRIDE.
// Warp layout: 8 warps = 2 row-halves (64 rows) x 4 col-groups (32 cols).
// ---------------------------------------------------------------------------
__device__ __forceinline__ void gemm_tile(const float* __restrict__ Asrc,
                                          const float* __restrict__ Bsrc,
                                          float acc[4][4][4],
                                          int mb, int nb, int gid, int cq) {
    #pragma unroll
    for (int ks = 0; ks < 16; ks++) {
        const int kA = ks * 8;
        uint32_t b0[4], b1[4];
        const float* Bk = Bsrc + (kA + cq) * W_STRIDE + nb + gid;
        #pragma unroll
        for (int nt = 0; nt < 4; nt++) {
            b0[nt] = __float_as_uint(Bk[nt*8]);
            b1[nt] = __float_as_uint(Bk[4*W_STRIDE + nt*8]);
        }
        #pragma unroll
        for (int mt = 0; mt < 4; mt++) {
            const float* Ar = Asrc + (mb + mt*16 + gid) * A_STRIDE + kA + cq;
            uint32_t a0 = __float_as_uint(Ar[0]);
            uint32_t a1 = __float_as_uint(Ar[8*A_STRIDE]);
            uint32_t a2 = __float_as_uint(Ar[4]);
            uint32_t a3 = __float_as_uint(Ar[8*A_STRIDE + 4]);
            #pragma unroll
            for (int nt = 0; nt < 4; nt++)
                mma_tf32(acc[mt][nt], a0, a1, a2, a3, b0[nt], b1[nt]);
        }
    }
}

// Prefetch one tile's 64KB feature block into registers (16 LDG.128/thread).
// For fixed tid: idx = tid + j*256 -> d1 = j>>1 (compile-time), r = tid + (j&1)*256.
__device__ __forceinline__ void load_feat(const float* __restrict__ x, int t, int g0,
                                          int tid, float4 pf[16]) {
    #pragma unroll
    for (int j = 0; j < 16; j++) {
        const int d1 = j >> 1;
        const int r  = (j & 1) * 256 + tid;
        pf[j] = *(const float4*)(
            x + (((size_t)(t - 1 - d1)) * NGRID + g0) * 16 + (size_t)r * 4);
    }
}

// ---------------------------------------------------------------------------
// Persistent main kernel. 1 CTA/SM, 256 threads. Weights resident in SMEM.
// Feature tile for iteration i+1 is prefetched into registers while GEMMs of
// iteration i run, so the global-load latency never sits between two barriers.
// ---------------------------------------------------------------------------
__global__ __launch_bounds__(256, 1)
void narx_main(const float* __restrict__ x, float* __restrict__ out) {
    extern __shared__ float sm[];
    float* W1s   = sm;                       // [128][W_STRIDE]
    float* W2s   = W1s + 128*W_STRIDE;       // [128][W_STRIDE]
    float* As    = W2s + 128*W_STRIDE;       // [128][A_STRIDE]  feat / h_in tile
    float* b1s   = As + 128*A_STRIDE;
    float* b2s   = b1s + 128;
    float* wouts = b2s + 128;
    float* yts   = wouts + 128;

    const int tid  = threadIdx.x;
    const int warp = tid >> 5;
    const int lane = tid & 31;
    const int gid  = lane >> 2;   // 0..7
    const int cq   = lane & 3;    // 0..3
    const int mb   = (warp >> 2) * 64;   // row base (0 or 64)
    const int nb   = (warp & 3) * 32;    // col base (0,32,64,96)

    // Load weights once per CTA (persistent)
    for (int i = tid; i < 128*128; i += 256) {
        int k = i >> 7, h = i & 127;
        W1s[k*W_STRIDE + h] = g_W1[i];
        W2s[k*W_STRIDE + h] = g_W2[i];
    }
    if (tid < 128) { b1s[tid] = g_b1[tid]; b2s[tid] = g_b2[tid]; wouts[tid] = g_wout[tid]; }
    __syncthreads();

    const float bout = g_bout[0];

    int tile = blockIdx.x;
    float4 pf[16];
    if (tile < NTILES) {
        load_feat(x, MAXD + (tile >> 4), (tile & 15) * 128, tid, pf);
    }

    for (; tile < NTILES; tile += gridDim.x) {
        const int t  = MAXD + (tile >> 4);
        const int g0 = (tile & 15) * 128;

        if (tid < 128) yts[tid] = 0.f;

        // Commit prefetched feature block to SMEM (tf32-rounded).
        // Layout: col block d1 holds x[t-1-d1, g0:g0+128, 0:16].
        #pragma unroll
        for (int j = 0; j < 16; j++) {
            const int d1 = j >> 1;
            const int r  = (j & 1) * 256 + tid;
            const int g  = r >> 2;
            const int c  = (r & 3) * 4;
            float4 w;
            w.x = __uint_as_float(f2tf32(pf[j].x));
            w.y = __uint_as_float(f2tf32(pf[j].y));
            w.z = __uint_as_float(f2tf32(pf[j].z));
            w.w = __uint_as_float(f2tf32(pf[j].w));
            *(float4*)(As + g*A_STRIDE + d1*16 + c) = w;
        }
        __syncthreads();   // feat ready, yts zeroed

        // Kick off next tile's global loads; latency hidden under both GEMMs.
        const int nxt = tile + gridDim.x;
        if (nxt < NTILES) {
            load_feat(x, MAXD + (nxt >> 4), (nxt & 15) * 128, tid, pf);
        }

        // ---- GEMM1: h_pre_in = feat @ Wc^T ----
        float acc[4][4][4];
        #pragma unroll
        for (int mt = 0; mt < 4; mt++)
            #pragma unroll
            for (int nt = 0; nt < 4; nt++)
                #pragma unroll
                for (int q = 0; q < 4; q++) acc[mt][nt][q] = 0.f;

        gemm_tile(As, W1s, acc, mb, nb, gid, cq);
        __syncthreads();   // all feat reads done before overwrite

        // Epilogue1: relu(.+b_in) -> tf32, write h_in back into As
        #pragma unroll
        for (int mt = 0; mt < 4; mt++) {
            int r = mb + mt*16 + gid;
            #pragma unroll
            for (int nt = 0; nt < 4; nt++) {
                int col = nb + nt*8 + 2*cq;
                float bb0 = b1s[col], bb1 = b1s[col+1];
                float2 v0, v1;
                v0.x = __uint_as_float(f2tf32(fmaxf(acc[mt][nt][0] + bb0, 0.f)));
                v0.y = __uint_as_float(f2tf32(fmaxf(acc[mt][nt][1] + bb1, 0.f)));
                v1.x = __uint_as_float(f2tf32(fmaxf(acc[mt][nt][2] + bb0, 0.f)));
                v1.y = __uint_as_float(f2tf32(fmaxf(acc[mt][nt][3] + bb1, 0.f)));
                *(float2*)(As + (size_t)r*A_STRIDE + col)     = v0;
                *(float2*)(As + (size_t)(r+8)*A_STRIDE + col) = v1;
            }
        }
        __syncthreads();   // h_in tile ready

        // ---- GEMM2: h_pre = h_in @ W_ih^T ----
        #pragma unroll
        for (int mt = 0; mt < 4; mt++)
            #pragma unroll
            for (int nt = 0; nt < 4; nt++)
                #pragma unroll
                for (int q = 0; q < 4; q++) acc[mt][nt][q] = 0.f;

        gemm_tile(As, W2s, acc, mb, nb, gid, cq);

        // Epilogue2: tanh(.+b2) (MUFU), fused W_out dot, shfl + shared-atomic reduce
        #pragma unroll
        for (int mt = 0; mt < 4; mt++) {
            float p0 = 0.f, p1 = 0.f;
            #pragma unroll
            for (int nt = 0; nt < 4; nt++) {
                int col = nb + nt*8 + 2*cq;
                float w0 = wouts[col], w1 = wouts[col+1];
                float bb0 = b2s[col], bb1 = b2s[col+1];
                p0 += fast_tanh(acc[mt][nt][0] + bb0) * w0
                    + fast_tanh(acc[mt][nt][1] + bb1) * w1;
                p1 += fast_tanh(acc[mt][nt][2] + bb0) * w0
                    + fast_tanh(acc[mt][nt][3] + bb1) * w1;
            }
            p0 += __shfl_xor_sync(0xffffffffu, p0, 1);
            p0 += __shfl_xor_sync(0xffffffffu, p0, 2);
            p1 += __shfl_xor_sync(0xffffffffu, p1, 1);
            p1 += __shfl_xor_sync(0xffffffffu, p1, 2);
            if (cq == 0) {
                int r = mb + mt*16 + gid;
                atomicAdd(&yts[r],     p0);
                atomicAdd(&yts[r + 8], p1);
            }
        }
        __syncthreads();   // atomics done; also fences As reads vs next-tile writes

        if (tid < 128)
            out[(size_t)t * NGRID + g0 + tid] = yts[tid] + bout;
        // yts[tid] re-zeroed by the same thread next iteration; As writes of the
        // next tile are ordered by the sync above.
    }
}

extern "C" void kernel_launch(void* const* d_in, const int* in_sizes, int n_in,
                              void* d_out, int out_size) {
    const float* x     = (const float*)d_in[0];
    const float* W_in  = (const float*)d_in[1];
    const float* b_in  = (const float*)d_in[2];
    const float* W_ih  = (const float*)d_in[3];
    const float* b_ih  = (const float*)d_in[4];
    /* d_in[5] = W_hh — dead in the reference (only b_hh is used) */
    const float* b_hh  = (const float*)d_in[6];
    const float* W_out = (const float*)d_in[7];
    const float* b_out = (const float*)d_in[8];
    float* out = (float*)d_out;

    cudaFuncSetAttribute(narx_main, cudaFuncAttributeMaxDynamicSharedMemorySize, SMEM_BYTES);
    int dev = 0, sms = 0;
    cudaGetDevice(&dev);
    cudaDeviceGetAttribute(&sms, cudaDevAttrMultiProcessorCount, dev);
    if (sms <= 0) sms = 148;

    prep_kernel<<<64, 256>>>(W_in, b_in, W_ih, b_ih, b_hh, W_out, b_out);
    head_kernel<<<(MAXD*NGRID + 255)/256, 256>>>(x, out);
    narx_main<<<sms, 256, SMEM_BYTES>>>(x, out);
}

// round 10
// speedup vs baseline: 1.6460x; 1.5253x over previous
#include <cuda_runtime.h>
#include <cuda_fp16.h>
#include <cstdint>
#include <cstddef>

// Problem constants (fixed by the reference)
#define NTT    1024
#define NGRID  2048
#define MAXD   8
#define TROWS  (NTT - MAXD)          // 1016 computed time rows
#define NTILES (TROWS * (NGRID/128)) // 16256 tiles of 128 g-rows

// fp16 SMEM strides in __half units. Row = 128 halves data + 8 pad = 136.
// Word index = row*68 + k/2; 68 mod 32 = 4 -> every warp fragment access is
// (4*gid + cq) mod 32: all 32 lanes distinct -> conflict-free LDS/STS.
#define A_STRIDE 136
#define W_STRIDE 136
// Layout: W1 | W2 | A (each 128*136 halves) then fp32 b1,b2,wout,yts
#define SMEM_HALVES (3*128*136)
#define SMEM_BYTES  (SMEM_HALVES*2 + 4*128*4)   // 104,448 + 2,048 = 106,496 B

// tanh(x) = 1 - 2/(exp(2x)+1) via MUFU ex2 + MUFU rcp (~1e-7 rel err)
__device__ __forceinline__ float fast_tanh(float x) {
    float e;
    asm("ex2.approx.f32 %0, %1;" : "=f"(e) : "f"(x * 2.885390081777927f)); // 2*log2(e)
    float r;
    asm("rcp.approx.f32 %0, %1;" : "=f"(r) : "f"(e + 1.0f));
    return fmaf(-2.0f, r, 1.0f);
}

// m16n8k16 fp16 MMA, fp32 accumulate (2x FLOP/instr vs tf32 m16n8k8)
__device__ __forceinline__ void mma_f16(float d[4],
                                        uint32_t a0, uint32_t a1, uint32_t a2, uint32_t a3,
                                        uint32_t b0, uint32_t b1) {
    asm volatile(
        "mma.sync.aligned.m16n8k16.row.col.f32.f16.f16.f32 "
        "{%0,%1,%2,%3}, {%4,%5,%6,%7}, {%8,%9}, {%0,%1,%2,%3};"
        : "+f"(d[0]), "+f"(d[1]), "+f"(d[2]), "+f"(d[3])
        : "r"(a0), "r"(a1), "r"(a2), "r"(a3), "r"(b0), "r"(b1));
}

// ---------------------------------------------------------------------------
// Fragment loader for one K-step (K=16 slice) of the 128x128x128 fp16 tile.
// A: [row][k] halves, stride A_STRIDE.  B: [n][k] halves, stride W_STRIDE.
// PTX m16n8k16 row.col layouts (g = lane>>2, cq = lane&3, k0 = 16*ks + 2*cq):
//   A: a0=(g,k0..k0+1) a1=(g+8,k0..) a2=(g,k0+8..) a3=(g+8,k0+8..)
//   B: b0=(k0..k0+1, n) b1=(k0+8..k0+9, n)  -> single LDS.b32 from [n][k]
// ---------------------------------------------------------------------------
__device__ __forceinline__ void ld_frags(const __half* __restrict__ Asrc,
                                         const __half* __restrict__ Bsrc,
                                         int ks, int mb, int nb, int gid, int cq,
                                         uint32_t a[4][4], uint32_t b0[4], uint32_t b1[4]) {
    const int k0 = ks * 16 + cq * 2;
    const __half* Bk = Bsrc + (nb + gid) * W_STRIDE + k0;
    #pragma unroll
    for (int nt = 0; nt < 4; nt++) {
        b0[nt] = *(const uint32_t*)(Bk + nt * 8 * W_STRIDE);
        b1[nt] = *(const uint32_t*)(Bk + nt * 8 * W_STRIDE + 8);
    }
    #pragma unroll
    for (int mt = 0; mt < 4; mt++) {
        const __half* Ar = Asrc + (mb + mt*16 + gid) * A_STRIDE + k0;
        a[mt][0] = *(const uint32_t*)(Ar);
        a[mt][1] = *(const uint32_t*)(Ar + 8 * A_STRIDE);
        a[mt][2] = *(const uint32_t*)(Ar + 8);
        a[mt][3] = *(const uint32_t*)(Ar + 8 * A_STRIDE + 8);
    }
}

// 128x128x128 fp16 GEMM tile, 8 K-steps of 16, 2-stage fragment pipeline:
// fragments for K-step ks+1 load before ks's MMAs issue, hiding LDS latency.
__device__ __forceinline__ void gemm_tile(const __half* __restrict__ Asrc,
                                          const __half* __restrict__ Bsrc,
                                          float acc[4][4][4],
                                          int mb, int nb, int gid, int cq) {
    uint32_t a[2][4][4], b0[2][4], b1[2][4];
    ld_frags(Asrc, Bsrc, 0, mb, nb, gid, cq, a[0], b0[0], b1[0]);
    #pragma unroll
    for (int ks = 0; ks < 8; ks++) {
        const int cur = ks & 1;
        if (ks < 7)
            ld_frags(Asrc, Bsrc, ks + 1, mb, nb, gid, cq,
                     a[cur ^ 1], b0[cur ^ 1], b1[cur ^ 1]);
        #pragma unroll
        for (int mt = 0; mt < 4; mt++)
            #pragma unroll
            for (int nt = 0; nt < 4; nt++)
                mma_f16(acc[mt][nt],
                        a[cur][mt][0], a[cur][mt][1], a[cur][mt][2], a[cur][mt][3],
                        b0[cur][nt], b1[cur][nt]);
    }
}

// Prefetch one tile's 64KB feature block into registers (16 LDG.128/thread).
__device__ __forceinline__ void load_feat(const float* __restrict__ x, int t, int g0,
                                          int tid, float4 pf[16]) {
    #pragma unroll
    for (int j = 0; j < 16; j++) {
        const int d1 = j >> 1;
        const int r  = (j & 1) * 256 + tid;
        pf[j] = *(const float4*)(
            x + (((size_t)(t - 1 - d1)) * NGRID + g0) * 16 + (size_t)r * 4);
    }
}

// ---------------------------------------------------------------------------
// SINGLE persistent kernel: per-CTA weight fold (prep), head passthrough, and
// the tiled 3-layer MLP (fp16 tensor cores, fp32 accumulate).
// One launch per kernel_launch call -> ncu -s 5 -c 1 captures THIS kernel.
// ---------------------------------------------------------------------------
__global__ __launch_bounds__(256, 1)
void narx_main(const float* __restrict__ x,
               const float* __restrict__ W_in,  const float* __restrict__ b_in,
               const float* __restrict__ W_ih,  const float* __restrict__ b_ih,
               const float* __restrict__ b_hh,  const float* __restrict__ W_out,
               const float* __restrict__ b_out, float* __restrict__ out) {
    extern __shared__ __half smh[];
    __half* W1s = smh;                      // [h=128][k] stride W_STRIDE (folded W_in)
    __half* W2s = W1s + 128*W_STRIDE;       // [h=128][k] = W_ih (row-major [n][k])
    __half* As  = W2s + 128*W_STRIDE;       // [row=128][k] feat / h_in tile
    float* b1s   = (float*)(smh + SMEM_HALVES);
    float* b2s   = b1s + 128;
    float* wouts = b2s + 128;
    float* yts   = wouts + 128;

    const int tid  = threadIdx.x;
    const int warp = tid >> 5;
    const int lane = tid & 31;
    const int gid  = lane >> 2;   // group id 0..7
    const int cq   = lane & 3;    // quad 0..3
    const int mb   = (warp >> 2) * 64;   // row base (0 or 64)
    const int nb   = (warp & 3) * 32;    // col base (0,32,64,96)

    // ---- head passthrough: out[0:8, :, 0] = x[0:8, :, 15] (striped) ----
    for (int i = blockIdx.x * 256 + tid; i < MAXD * NGRID; i += gridDim.x * 256)
        out[i] = x[(size_t)i * 16 + 15];

    // ---- per-CTA prep: fold W_in (128x144, dup offset -1) into W1s[h][k],
    //      copy W_ih into W2s[h][k]; fp16-round. L2-broadcast reads. ----
    for (int i = tid; i < 128*128; i += 256) {
        int h = i >> 7, k = i & 127;
        int d = (k >> 4) + 1;   // delay 1..8
        int c = k & 15;         // channel 0..15 (15 == yf channel)
        int j = 9 - d;          // 1..8
        float v;
        if (c < 15) {
            v = W_in[h*144 + j*15 + c];
            if (d == 1) v += W_in[h*144 + c];          // duplicate offset -1 (j=0)
        } else {
            v = W_in[h*144 + 135 + j];
            if (d == 1) v += W_in[h*144 + 135];
        }
        W1s[h*W_STRIDE + k] = __float2half_rn(v);
        W2s[h*W_STRIDE + k] = __float2half_rn(W_ih[h*128 + k]);
    }
    if (tid < 128) {
        b1s[tid]   = b_in[tid];
        b2s[tid]   = b_ih[tid] + b_hh[tid];
        wouts[tid] = W_out[tid];
    }
    __syncthreads();

    const float bout = b_out[0];

    int tile = blockIdx.x;
    float4 pf[16];
    if (tile < NTILES)
        load_feat(x, MAXD + (tile >> 4), (tile & 15) * 128, tid, pf);

    for (; tile < NTILES; tile += gridDim.x) {
        const int t  = MAXD + (tile >> 4);
        const int g0 = (tile & 15) * 128;

        if (tid < 128) yts[tid] = 0.f;

        // Commit prefetched feature block to SMEM as fp16.
        // Layout: col block d1 holds x[t-1-d1, g0:g0+128, 0:16].
        #pragma unroll
        for (int j = 0; j < 16; j++) {
            const int d1 = j >> 1;
            const int r  = (j & 1) * 256 + tid;
            const int g  = r >> 2;
            const int c  = (r & 3) * 4;
            __half2 lo = __floats2half2_rn(pf[j].x, pf[j].y);
            __half2 hi = __floats2half2_rn(pf[j].z, pf[j].w);
            uint2 pk;
            pk.x = *(uint32_t*)&lo;
            pk.y = *(uint32_t*)&hi;
            *(uint2*)(As + g*A_STRIDE + d1*16 + c) = pk;   // half-offset %4==0 -> 8B aligned
        }
        __syncthreads();   // feat ready, yts zeroed

        // Kick off next tile's global loads; latency hidden under both GEMMs.
        const int nxt = tile + gridDim.x;
        if (nxt < NTILES)
            load_feat(x, MAXD + (nxt >> 4), (nxt & 15) * 128, tid, pf);

        // ---- GEMM1: h_pre_in = feat @ Wc^T ----
        float acc[4][4][4];
        #pragma unroll
        for (int mt = 0; mt < 4; mt++)
            #pragma unroll
            for (int nt = 0; nt < 4; nt++)
                #pragma unroll
                for (int q = 0; q < 4; q++) acc[mt][nt][q] = 0.f;

        gemm_tile(As, W1s, acc, mb, nb, gid, cq);
        __syncthreads();   // all feat reads done before overwrite

        // Epilogue1: relu(.+b_in) -> fp16, write h_in back into As.
        // C layout m16n8: {(r,col),(r,col+1),(r+8,col),(r+8,col+1)}, col=nb+nt*8+2cq
        #pragma unroll
        for (int mt = 0; mt < 4; mt++) {
            int r = mb + mt*16 + gid;
            #pragma unroll
            for (int nt = 0; nt < 4; nt++) {
                int col = nb + nt*8 + 2*cq;
                float bb0 = b1s[col], bb1 = b1s[col+1];
                __half2 v0 = __floats2half2_rn(fmaxf(acc[mt][nt][0] + bb0, 0.f),
                                               fmaxf(acc[mt][nt][1] + bb1, 0.f));
                __half2 v1 = __floats2half2_rn(fmaxf(acc[mt][nt][2] + bb0, 0.f),
                                               fmaxf(acc[mt][nt][3] + bb1, 0.f));
                *(__half2*)(As + (size_t)r*A_STRIDE + col)     = v0;
                *(__half2*)(As + (size_t)(r+8)*A_STRIDE + col) = v1;
            }
        }
        __syncthreads();   // h_in tile ready

        // ---- GEMM2: h_pre = h_in @ W_ih^T ----
        #pragma unroll
        for (int mt = 0; mt < 4; mt++)
            #pragma unroll
            for (int nt = 0; nt < 4; nt++)
                #pragma unroll
                for (int q = 0; q < 4; q++) acc[mt][nt][q] = 0.f;

        gemm_tile(As, W2s, acc, mb, nb, gid, cq);

        // Epilogue2: tanh(.+b2) (MUFU), fused W_out dot, shfl + shared-atomic reduce
        #pragma unroll
        for (int mt = 0; mt < 4; mt++) {
            float p0 = 0.f, p1 = 0.f;
            #pragma unroll
            for (int nt = 0; nt < 4; nt++) {
                int col = nb + nt*8 + 2*cq;
                float w0 = wouts[col], w1 = wouts[col+1];
                float bb0 = b2s[col], bb1 = b2s[col+1];
                p0 += fast_tanh(acc[mt][nt][0] + bb0) * w0
                    + fast_tanh(acc[mt][nt][1] + bb1) * w1;
                p1 += fast_tanh(acc[mt][nt][2] + bb0) * w0
                    + fast_tanh(acc[mt][nt][3] + bb1) * w1;
            }
            p0 += __shfl_xor_sync(0xffffffffu, p0, 1);
            p0 += __shfl_xor_sync(0xffffffffu, p0, 2);
            p1 += __shfl_xor_sync(0xffffffffu, p1, 1);
            p1 += __shfl_xor_sync(0xffffffffu, p1, 2);
            if (cq == 0) {
                int r = mb + mt*16 + gid;
                atomicAdd(&yts[r],     p0);
                atomicAdd(&yts[r + 8], p1);
            }
        }
        __syncthreads();   // atomics done; also fences As reads vs next-tile writes

        if (tid < 128)
            out[(size_t)t * NGRID + g0 + tid] = yts[tid] + bout;
        // yts[tid] re-zeroed by the same thread next iteration; As writes of the
        // next tile are ordered by the sync above.
    }
}

extern "C" void kernel_launch(void* const* d_in, const int* in_sizes, int n_in,
                              void* d_out, int out_size) {
    const float* x     = (const float*)d_in[0];
    const float* W_in  = (const float*)d_in[1];
    const float* b_in  = (const float*)d_in[2];
    const float* W_ih  = (const float*)d_in[3];
    const float* b_ih  = (const float*)d_in[4];
    /* d_in[5] = W_hh — dead in the reference (only b_hh is used) */
    const float* b_hh  = (const float*)d_in[6];
    const float* W_out = (const float*)d_in[7];
    const float* b_out = (const float*)d_in[8];
    float* out = (float*)d_out;

    cudaFuncSetAttribute(narx_main, cudaFuncAttributeMaxDynamicSharedMemorySize, SMEM_BYTES);
    int dev = 0, sms = 0;
    cudaGetDevice(&dev);
    cudaDeviceGetAttribute(&sms, cudaDevAttrMultiProcessorCount, dev);
    if (sms <= 0) sms = 148;

    narx_main<<<sms, 256, SMEM_BYTES>>>(x, W_in, b_in, W_ih, b_ih, b_hh,
                                        W_out, b_out, out);
}

// round 11
// speedup vs baseline: 1.7691x; 1.0748x over previous
#include <cuda_runtime.h>
#include <cuda_fp16.h>
#include <cstdint>
#include <cstddef>

// Problem constants (fixed by the reference)
#define NTT    1024
#define NGRID  2048
#define MAXD   8
#define TROWS  (NTT - MAXD)          // 1016 computed time rows
#define NTILES (TROWS * (NGRID/128)) // 16256 tiles of 128 g-rows

#define NTHREADS 512                 // 16 warps, 4 per SMSP (was 8/2)

// fp16 SMEM strides in __half units. Row = 128 halves data + 8 pad = 136.
// Word index = row*68 + k/2; 68 mod 32 = 4 -> warp fragment accesses map to
// (4*(row mod 8) + cq) mod 32: all 32 lanes distinct -> conflict-free LDS/STS.
#define A_STRIDE 136
#define W_STRIDE 136
// Layout: W1 | W2 | A (each 128*136 halves) then fp32 b1,b2,wout,yts
#define SMEM_HALVES (3*128*136)
#define SMEM_BYTES  (SMEM_HALVES*2 + 4*128*4)   // 104,448 + 2,048 = 106,496 B

// tanh(x) = 1 - 2/(exp(2x)+1) via MUFU ex2 + MUFU rcp (~1e-7 rel err)
__device__ __forceinline__ float fast_tanh(float x) {
    float e;
    asm("ex2.approx.f32 %0, %1;" : "=f"(e) : "f"(x * 2.885390081777927f)); // 2*log2(e)
    float r;
    asm("rcp.approx.f32 %0, %1;" : "=f"(r) : "f"(e + 1.0f));
    return fmaf(-2.0f, r, 1.0f);
}

// m16n8k16 fp16 MMA, fp32 accumulate
__device__ __forceinline__ void mma_f16(float d[4],
                                        uint32_t a0, uint32_t a1, uint32_t a2, uint32_t a3,
                                        uint32_t b0, uint32_t b1) {
    asm volatile(
        "mma.sync.aligned.m16n8k16.row.col.f32.f16.f16.f32 "
        "{%0,%1,%2,%3}, {%4,%5,%6,%7}, {%8,%9}, {%0,%1,%2,%3};"
        : "+f"(d[0]), "+f"(d[1]), "+f"(d[2]), "+f"(d[3])
        : "r"(a0), "r"(a1), "r"(a2), "r"(a3), "r"(b0), "r"(b1));
}

// ---------------------------------------------------------------------------
// Fragment loader for one K-step (K=16 slice). Warp owns a 32-row x 32-col
// sub-tile: mt in {0,1} (16-row halves), nt in {0..3} (8-col groups).
// A: [row][k] halves, stride A_STRIDE.  B: [n][k] halves, stride W_STRIDE.
// PTX m16n8k16 row.col layouts (g = lane>>2, cq = lane&3, k0 = 16*ks + 2*cq):
//   A: a0=(g,k0..k0+1) a1=(g+8,k0..) a2=(g,k0+8..) a3=(g+8,k0+8..)
//   B: b0=(k0..k0+1, n) b1=(k0+8..k0+9, n)  -> single LDS.b32 from [n][k]
// ---------------------------------------------------------------------------
__device__ __forceinline__ void ld_frags(const __half* __restrict__ Asrc,
                                         const __half* __restrict__ Bsrc,
                                         int ks, int mb, int nb, int gid, int cq,
                                         uint32_t a[2][4], uint32_t b0[4], uint32_t b1[4]) {
    const int k0 = ks * 16 + cq * 2;
    const __half* Bk = Bsrc + (nb + gid) * W_STRIDE + k0;
    #pragma unroll
    for (int nt = 0; nt < 4; nt++) {
        b0[nt] = *(const uint32_t*)(Bk + nt * 8 * W_STRIDE);
        b1[nt] = *(const uint32_t*)(Bk + nt * 8 * W_STRIDE + 8);
    }
    #pragma unroll
    for (int mt = 0; mt < 2; mt++) {
        const __half* Ar = Asrc + (mb + mt*16 + gid) * A_STRIDE + k0;
        a[mt][0] = *(const uint32_t*)(Ar);
        a[mt][1] = *(const uint32_t*)(Ar + 8 * A_STRIDE);
        a[mt][2] = *(const uint32_t*)(Ar + 8);
        a[mt][3] = *(const uint32_t*)(Ar + 8 * A_STRIDE + 8);
    }
}

// 32x32 warp sub-tile of the 128x128x128 fp16 GEMM, 8 K-steps of 16,
// 2-stage fragment pipeline (K-step ks+1 loads before ks's MMAs issue).
__device__ __forceinline__ void gemm_tile(const __half* __restrict__ Asrc,
                                          const __half* __restrict__ Bsrc,
                                          float acc[2][4][4],
                                          int mb, int nb, int gid, int cq) {
    uint32_t a[2][2][4], b0[2][4], b1[2][4];
    ld_frags(Asrc, Bsrc, 0, mb, nb, gid, cq, a[0], b0[0], b1[0]);
    #pragma unroll
    for (int ks = 0; ks < 8; ks++) {
        const int cur = ks & 1;
        if (ks < 7)
            ld_frags(Asrc, Bsrc, ks + 1, mb, nb, gid, cq,
                     a[cur ^ 1], b0[cur ^ 1], b1[cur ^ 1]);
        #pragma unroll
        for (int mt = 0; mt < 2; mt++)
            #pragma unroll
            for (int nt = 0; nt < 4; nt++)
                mma_f16(acc[mt][nt],
                        a[cur][mt][0], a[cur][mt][1], a[cur][mt][2], a[cur][mt][3],
                        b0[cur][nt], b1[cur][nt]);
    }
}

// Prefetch one tile's 64KB feature block: 8 LDG.128/thread at 512 threads.
// Slab j (= delay index d1) is 512 float4; thread tid takes float4 #tid.
__device__ __forceinline__ void load_feat(const float* __restrict__ x, int t, int g0,
                                          int tid, float4 pf[8]) {
    #pragma unroll
    for (int j = 0; j < 8; j++)
        pf[j] = *(const float4*)(
            x + (((size_t)(t - 1 - j)) * NGRID + g0) * 16 + (size_t)tid * 4);
}

// ---------------------------------------------------------------------------
// SINGLE persistent kernel, 512 threads (16 warps): per-CTA weight fold,
// head passthrough, tiled 3-layer MLP (fp16 MMA, fp32 accumulate).
// 4 warps/SMSP so LDS/MUFU/STS of one warp overlaps HMMA of another.
// ---------------------------------------------------------------------------
__global__ __launch_bounds__(NTHREADS, 1)
void narx_main(const float* __restrict__ x,
               const float* __restrict__ W_in,  const float* __restrict__ b_in,
               const float* __restrict__ W_ih,  const float* __restrict__ b_ih,
               const float* __restrict__ b_hh,  const float* __restrict__ W_out,
               const float* __restrict__ b_out, float* __restrict__ out) {
    extern __shared__ __half smh[];
    __half* W1s = smh;                      // [h=128][k] stride W_STRIDE (folded W_in)
    __half* W2s = W1s + 128*W_STRIDE;       // [h=128][k] = W_ih (row-major [n][k])
    __half* As  = W2s + 128*W_STRIDE;       // [row=128][k] feat / h_in tile
    float* b1s   = (float*)(smh + SMEM_HALVES);
    float* b2s   = b1s + 128;
    float* wouts = b2s + 128;
    float* yts   = wouts + 128;

    const int tid  = threadIdx.x;
    const int warp = tid >> 5;
    const int lane = tid & 31;
    const int gid  = lane >> 2;   // group id 0..7
    const int cq   = lane & 3;    // quad 0..3
    const int mb   = (warp >> 2) * 32;   // row base: 0,32,64,96
    const int nb   = (warp & 3) * 32;    // col base: 0,32,64,96

    // ---- head passthrough: out[0:8, :, 0] = x[0:8, :, 15] (striped) ----
    for (int i = blockIdx.x * NTHREADS + tid; i < MAXD * NGRID; i += gridDim.x * NTHREADS)
        out[i] = x[(size_t)i * 16 + 15];

    // ---- per-CTA prep: fold W_in (128x144, dup offset -1) into W1s[h][k],
    //      copy W_ih into W2s[h][k]; fp16-round. L2-broadcast reads. ----
    for (int i = tid; i < 128*128; i += NTHREADS) {
        int h = i >> 7, k = i & 127;
        int d = (k >> 4) + 1;   // delay 1..8
        int c = k & 15;         // channel 0..15 (15 == yf channel)
        int j = 9 - d;          // 1..8
        float v;
        if (c < 15) {
            v = W_in[h*144 + j*15 + c];
            if (d == 1) v += W_in[h*144 + c];          // duplicate offset -1 (j=0)
        } else {
            v = W_in[h*144 + 135 + j];
            if (d == 1) v += W_in[h*144 + 135];
        }
        W1s[h*W_STRIDE + k] = __float2half_rn(v);
        W2s[h*W_STRIDE + k] = __float2half_rn(W_ih[h*128 + k]);
    }
    if (tid < 128) {
        b1s[tid]   = b_in[tid];
        b2s[tid]   = b_ih[tid] + b_hh[tid];
        wouts[tid] = W_out[tid];
    }
    __syncthreads();

    const float bout = b_out[0];

    int tile = blockIdx.x;
    float4 pf[8];
    if (tile < NTILES)
        load_feat(x, MAXD + (tile >> 4), (tile & 15) * 128, tid, pf);

    for (; tile < NTILES; tile += gridDim.x) {
        const int t  = MAXD + (tile >> 4);
        const int g0 = (tile & 15) * 128;

        if (tid < 128) yts[tid] = 0.f;

        // Commit prefetched feature block to SMEM as fp16.
        // Layout: col block j (delay) holds x[t-1-j, g0:g0+128, 0:16].
        {
            const int g = tid >> 2;
            const int c = (tid & 3) * 4;
            #pragma unroll
            for (int j = 0; j < 8; j++) {
                __half2 lo = __floats2half2_rn(pf[j].x, pf[j].y);
                __half2 hi = __floats2half2_rn(pf[j].z, pf[j].w);
                uint2 pk;
                pk.x = *(uint32_t*)&lo;
                pk.y = *(uint32_t*)&hi;
                *(uint2*)(As + g*A_STRIDE + j*16 + c) = pk;  // half-offset %4==0 -> 8B aligned
            }
        }
        __syncthreads();   // feat ready, yts zeroed

        // Kick off next tile's global loads; latency hidden under both GEMMs.
        const int nxt = tile + gridDim.x;
        if (nxt < NTILES)
            load_feat(x, MAXD + (nxt >> 4), (nxt & 15) * 128, tid, pf);

        // ---- GEMM1: h_pre_in = feat @ Wc^T ----
        float acc[2][4][4];
        #pragma unroll
        for (int mt = 0; mt < 2; mt++)
            #pragma unroll
            for (int nt = 0; nt < 4; nt++)
                #pragma unroll
                for (int q = 0; q < 4; q++) acc[mt][nt][q] = 0.f;

        gemm_tile(As, W1s, acc, mb, nb, gid, cq);
        __syncthreads();   // all feat reads done before overwrite

        // Epilogue1: relu(.+b_in) -> fp16, write h_in back into As.
        // C layout m16n8: {(r,col),(r,col+1),(r+8,col),(r+8,col+1)}, col=nb+nt*8+2cq
        #pragma unroll
        for (int mt = 0; mt < 2; mt++) {
            int r = mb + mt*16 + gid;
            #pragma unroll
            for (int nt = 0; nt < 4; nt++) {
                int col = nb + nt*8 + 2*cq;
                float bb0 = b1s[col], bb1 = b1s[col+1];
                __half2 v0 = __floats2half2_rn(fmaxf(acc[mt][nt][0] + bb0, 0.f),
                                               fmaxf(acc[mt][nt][1] + bb1, 0.f));
                __half2 v1 = __floats2half2_rn(fmaxf(acc[mt][nt][2] + bb0, 0.f),
                                               fmaxf(acc[mt][nt][3] + bb1, 0.f));
                *(__half2*)(As + (size_t)r*A_STRIDE + col)     = v0;
                *(__half2*)(As + (size_t)(r+8)*A_STRIDE + col) = v1;
            }
        }
        __syncthreads();   // h_in tile ready

        // ---- GEMM2: h_pre = h_in @ W_ih^T ----
        #pragma unroll
        for (int mt = 0; mt < 2; mt++)
            #pragma unroll
            for (int nt = 0; nt < 4; nt++)
                #pragma unroll
                for (int q = 0; q < 4; q++) acc[mt][nt][q] = 0.f;

        gemm_tile(As, W2s, acc, mb, nb, gid, cq);

        // Epilogue2: tanh(.+b2) (MUFU), fused W_out dot, shfl + shared-atomic reduce
        #pragma unroll
        for (int mt = 0; mt < 2; mt++) {
            float p0 = 0.f, p1 = 0.f;
            #pragma unroll
            for (int nt = 0; nt < 4; nt++) {
                int col = nb + nt*8 + 2*cq;
                float w0 = wouts[col], w1 = wouts[col+1];
                float bb0 = b2s[col], bb1 = b2s[col+1];
                p0 += fast_tanh(acc[mt][nt][0] + bb0) * w0
                    + fast_tanh(acc[mt][nt][1] + bb1) * w1;
                p1 += fast_tanh(acc[mt][nt][2] + bb0) * w0
                    + fast_tanh(acc[mt][nt][3] + bb1) * w1;
            }
            p0 += __shfl_xor_sync(0xffffffffu, p0, 1);
            p0 += __shfl_xor_sync(0xffffffffu, p0, 2);
            p1 += __shfl_xor_sync(0xffffffffu, p1, 1);
            p1 += __shfl_xor_sync(0xffffffffu, p1, 2);
            if (cq == 0) {
                int r = mb + mt*16 + gid;
                atomicAdd(&yts[r],     p0);   // 4 col-group partials per row
                atomicAdd(&yts[r + 8], p1);
            }
        }
        __syncthreads();   // atomics done; also fences As reads vs next-tile writes

        if (tid < 128)
            out[(size_t)t * NGRID + g0 + tid] = yts[tid] + bout;
        // yts[tid] re-zeroed by the same thread next iteration; As writes of the
        // next tile are ordered by the sync above.
    }
}

extern "C" void kernel_launch(void* const* d_in, const int* in_sizes, int n_in,
                              void* d_out, int out_size) {
    const float* x     = (const float*)d_in[0];
    const float* W_in  = (const float*)d_in[1];
    const float* b_in  = (const float*)d_in[2];
    const float* W_ih  = (const float*)d_in[3];
    const float* b_ih  = (const float*)d_in[4];
    /* d_in[5] = W_hh — dead in the reference (only b_hh is used) */
    const float* b_hh  = (const float*)d_in[6];
    const float* W_out = (const float*)d_in[7];
    const float* b_out = (const float*)d_in[8];
    float* out = (float*)d_out;

    cudaFuncSetAttribute(narx_main, cudaFuncAttributeMaxDynamicSharedMemorySize, SMEM_BYTES);
    int dev = 0, sms = 0;
    cudaGetDevice(&dev);
    cudaDeviceGetAttribute(&sms, cudaDevAttrMultiProcessorCount, dev);
    if (sms <= 0) sms = 148;

    narx_main<<<sms, NTHREADS, SMEM_BYTES>>>(x, W_in, b_in, W_ih, b_ih, b_hh,
                                             W_out, b_out, out);
}

// round 13
// speedup vs baseline: 1.7718x; 1.0015x over previous
#include <cuda_runtime.h>
#include <cuda_fp16.h>
#include <cstdint>
#include <cstddef>

// Problem constants (fixed by the reference)
#define NTT    1024
#define NGRID  2048
#define MAXD   8
#define TROWS  (NTT - MAXD)          // 1016 computed time rows
#define NTILES (TROWS * (NGRID/128)) // 16256 tiles of 128 g-rows

#define NTHREADS 512                 // 16 warps, 4 per SMSP

// fp16 SMEM strides in __half units. Row = 128 halves data + 8 pad = 136.
// Word index = row*68 + k/2; 68 mod 32 = 4 -> ldmatrix 8-row phases hit
// word-groups 4r mod 32 = all 32 banks exactly once -> conflict-free.
#define A_STRIDE 136
#define W_STRIDE 136
#define ROW_BYTES (A_STRIDE*2)       // 272
// Layout: W1 | W2 | A (each 128*136 halves) then fp32 b1,b2,wout,yts
#define SMEM_HALVES (3*128*136)
#define SMEM_BYTES  (SMEM_HALVES*2 + 4*128*4)   // 104,448 + 2,048 = 106,496 B

// tanh(x) = 1 - 2/(exp(2x)+1) via MUFU ex2 + MUFU rcp (~1e-7 rel err)
__device__ __forceinline__ float fast_tanh(float x) {
    float e;
    asm("ex2.approx.f32 %0, %1;" : "=f"(e) : "f"(x * 2.885390081777927f)); // 2*log2(e)
    float r;
    asm("rcp.approx.f32 %0, %1;" : "=f"(r) : "f"(e + 1.0f));
    return fmaf(-2.0f, r, 1.0f);
}

// m16n8k16 fp16 MMA, fp32 accumulate
__device__ __forceinline__ void mma_f16(float d[4],
                                        uint32_t a0, uint32_t a1, uint32_t a2, uint32_t a3,
                                        uint32_t b0, uint32_t b1) {
    asm volatile(
        "mma.sync.aligned.m16n8k16.row.col.f32.f16.f16.f32 "
        "{%0,%1,%2,%3}, {%4,%5,%6,%7}, {%8,%9}, {%0,%1,%2,%3};"
        : "+f"(d[0]), "+f"(d[1]), "+f"(d[2]), "+f"(d[3])
        : "r"(a0), "r"(a1), "r"(a2), "r"(a3), "r"(b0), "r"(b1));
}

// ldmatrix x4: one instruction loads 4 8x8 fp16 matrices (replaces 4 LDS.32/lane)
__device__ __forceinline__ void ldsm4(uint32_t r[4], uint32_t addr) {
    asm volatile("ldmatrix.sync.aligned.m8n8.x4.shared.b16 {%0,%1,%2,%3}, [%4];"
        : "=r"(r[0]), "=r"(r[1]), "=r"(r[2]), "=r"(r[3]) : "r"(addr));
}

__device__ __forceinline__ uint32_t smem_u32(const void* p) {
    uint32_t a;
    asm("{ .reg .u64 t; cvta.to.shared.u64 t, %1; cvt.u32.u64 %0, t; }"
        : "=r"(a) : "l"(p));
    return a;
}

// ---------------------------------------------------------------------------
// 32x32 warp sub-tile of the 128x128x128 fp16 GEMM via ldmatrix.
// Per thread (p = lane&7, sel = lane>>3) address bases:
//   Aaddr: matrix sel -> rows mb + (sel&1)*8 + p, k-offset (sel>>1)*8 halves
//          regs {a0..a3} land exactly in m16n8k16 A-fragment order.
//   Baddr: matrix sel -> rows nb + sel*8 + p  => r[sel] = b0[nt=sel];
//          same +16B gives b1[nt=sel].
// 4 LDSM.x4 + 8 HMMA per K-step; single-stage (4 warps/SMSP hide latency).
// ---------------------------------------------------------------------------
__device__ __forceinline__ void gemm_tile(uint32_t Aaddr, uint32_t Baddr,
                                          float acc[2][4][4]) {
    #pragma unroll
    for (int ks = 0; ks < 8; ks++) {
        uint32_t a0[4], a1[4], b0[4], b1[4];
        ldsm4(b0, Baddr + ks*32);
        ldsm4(b1, Baddr + ks*32 + 16);
        ldsm4(a0, Aaddr + ks*32);
        ldsm4(a1, Aaddr + 16*ROW_BYTES + ks*32);   // mt=1: +16 rows
        #pragma unroll
        for (int nt = 0; nt < 4; nt++) {
            mma_f16(acc[0][nt], a0[0], a0[1], a0[2], a0[3], b0[nt], b1[nt]);
            mma_f16(acc[1][nt], a1[0], a1[1], a1[2], a1[3], b0[nt], b1[nt]);
        }
    }
}

// Prefetch one tile's 64KB feature block: 8 LDG.128/thread at 512 threads.
__device__ __forceinline__ void load_feat(const float* __restrict__ x, int t, int g0,
                                          int tid, float4 pf[8]) {
    #pragma unroll
    for (int j = 0; j < 8; j++)
        pf[j] = *(const float4*)(
            x + (((size_t)(t - 1 - j)) * NGRID + g0) * 16 + (size_t)tid * 4);
}

// ---------------------------------------------------------------------------
// SINGLE persistent kernel, 512 threads. Cross-tile software pipeline:
// epilogue2 (MUFU tanh) of tile i runs with NO barrier before GEMM1 of tile
// i+1, so tanh work hides under the next tile's tensor phase. Tile i's output
// store is deferred past GEMM1(i+1)'s barrier.
// ---------------------------------------------------------------------------
__global__ __launch_bounds__(NTHREADS, 1)
void narx_main(const float* __restrict__ x,
               const float* __restrict__ W_in,  const float* __restrict__ b_in,
               const float* __restrict__ W_ih,  const float* __restrict__ b_ih,
               const float* __restrict__ b_hh,  const float* __restrict__ W_out,
               const float* __restrict__ b_out, float* __restrict__ out) {
    extern __shared__ __half smh[];
    __half* W1s = smh;                      // [h=128][k] stride W_STRIDE (folded W_in)
    __half* W2s = W1s + 128*W_STRIDE;       // [h=128][k] = W_ih (row-major [n][k])
    __half* As  = W2s + 128*W_STRIDE;       // [row=128][k] feat / h_in tile
    float* b1s   = (float*)(smh + SMEM_HALVES);
    float* b2s   = b1s + 128;
    float* wouts = b2s + 128;
    float* yts   = wouts + 128;

    const int tid  = threadIdx.x;
    const int warp = tid >> 5;
    const int lane = tid & 31;
    const int gid  = lane >> 2;   // group id 0..7
    const int cq   = lane & 3;    // quad 0..3
    const int mb   = (warp >> 2) * 32;   // row base: 0,32,64,96
    const int nb   = (warp & 3) * 32;    // col base: 0,32,64,96

    // ldmatrix per-thread address bases
    const int p   = lane & 7;
    const int sel = lane >> 3;
    const uint32_t W1b = smem_u32(W1s), W2b = smem_u32(W2s), Asb = smem_u32(As);
    const uint32_t Aaddr  = Asb + (uint32_t)(mb + (sel & 1)*8 + p) * ROW_BYTES
                                + (uint32_t)(sel >> 1) * 16;
    const uint32_t B1addr = W1b + (uint32_t)(nb + sel*8 + p) * ROW_BYTES;
    const uint32_t B2addr = W2b + (uint32_t)(nb + sel*8 + p) * ROW_BYTES;

    // ---- head passthrough: out[0:8, :, 0] = x[0:8, :, 15] (striped) ----
    for (int i = blockIdx.x * NTHREADS + tid; i < MAXD * NGRID; i += gridDim.x * NTHREADS)
        out[i] = x[(size_t)i * 16 + 15];

    // ---- per-CTA prep: fold W_in (128x144, dup offset -1) into W1s[h][k],
    //      copy W_ih into W2s[h][k]; fp16-round. L2-broadcast reads. ----
    for (int i = tid; i < 128*128; i += NTHREADS) {
        int h = i >> 7, k = i & 127;
        int d = (k >> 4) + 1;   // delay 1..8
        int c = k & 15;         // channel 0..15 (15 == yf channel)
        int j = 9 - d;          // 1..8
        float v;
        if (c < 15) {
            v = W_in[h*144 + j*15 + c];
            if (d == 1) v += W_in[h*144 + c];          // duplicate offset -1 (j=0)
        } else {
            v = W_in[h*144 + 135 + j];
            if (d == 1) v += W_in[h*144 + 135];
        }
        W1s[h*W_STRIDE + k] = __float2half_rn(v);
        W2s[h*W_STRIDE + k] = __float2half_rn(W_ih[h*128 + k]);
    }
    if (tid < 128) {
        b1s[tid]   = b_in[tid];
        b2s[tid]   = b_ih[tid] + b_hh[tid];
        wouts[tid] = W_out[tid];
        yts[tid]   = 0.f;
    }

    const float bout = b_out[0];
    const int g  = tid >> 2;        // feat-commit row
    const int cc = (tid & 3) * 4;   // feat-commit col

    // Prologue: load + commit first tile's features
    int tile = blockIdx.x;
    float4 pf[8];
    if (tile < NTILES) {
        load_feat(x, MAXD + (tile >> 4), (tile & 15) * 128, tid, pf);
        #pragma unroll
        for (int j = 0; j < 8; j++) {
            __half2 lo = __floats2half2_rn(pf[j].x, pf[j].y);
            __half2 hi = __floats2half2_rn(pf[j].z, pf[j].w);
            uint2 pk; pk.x = *(uint32_t*)&lo; pk.y = *(uint32_t*)&hi;
            *(uint2*)(As + g*A_STRIDE + j*16 + cc) = pk;
        }
    }
    __syncthreads();   // feat0 + weights + yts ready

    int prev_t = -1, prev_g0 = 0;

    for (; tile < NTILES; tile += gridDim.x) {
        const int t  = MAXD + (tile >> 4);
        const int g0 = (tile & 15) * 128;

        // Prefetch next tile's features (consumed at end of this iteration)
        const int nxt = tile + gridDim.x;
        if (nxt < NTILES)
            load_feat(x, MAXD + (nxt >> 4), (nxt & 15) * 128, tid, pf);

        // ---- GEMM1: h_pre_in = feat @ Wc^T  (overlaps prev tile's epi2) ----
        float acc[2][4][4];
        #pragma unroll
        for (int mt = 0; mt < 2; mt++)
            #pragma unroll
            for (int nt = 0; nt < 4; nt++)
                #pragma unroll
                for (int q = 0; q < 4; q++) acc[mt][nt][q] = 0.f;

        gemm_tile(Aaddr, B1addr, acc);
        __syncthreads();   // As(feat) reads done; prev epi2 atomics visible

        // Deferred output store for previous tile, then re-zero yts
        if (tid < 128) {
            if (prev_t >= 0)
                out[(size_t)prev_t * NGRID + prev_g0 + tid] = yts[tid] + bout;
            yts[tid] = 0.f;
        }

        // Epilogue1: relu(.+b_in) -> fp16, write h_in back into As.
        #pragma unroll
        for (int mt = 0; mt < 2; mt++) {
            int r = mb + mt*16 + gid;
            #pragma unroll
            for (int nt = 0; nt < 4; nt++) {
                int col = nb + nt*8 + 2*cq;
                float bb0 = b1s[col], bb1 = b1s[col+1];
                __half2 v0 = __floats2half2_rn(fmaxf(acc[mt][nt][0] + bb0, 0.f),
                                               fmaxf(acc[mt][nt][1] + bb1, 0.f));
                __half2 v1 = __floats2half2_rn(fmaxf(acc[mt][nt][2] + bb0, 0.f),
                                               fmaxf(acc[mt][nt][3] + bb1, 0.f));
                *(__half2*)(As + (size_t)r*A_STRIDE + col)     = v0;
                *(__half2*)(As + (size_t)(r+8)*A_STRIDE + col) = v1;
            }
        }
        __syncthreads();   // h_in tile ready

        // ---- GEMM2: h_pre = h_in @ W_ih^T ----
        #pragma unroll
        for (int mt = 0; mt < 2; mt++)
            #pragma unroll
            for (int nt = 0; nt < 4; nt++)
                #pragma unroll
                for (int q = 0; q < 4; q++) acc[mt][nt][q] = 0.f;

        gemm_tile(Aaddr, B2addr, acc);
        __syncthreads();   // all h_in reads done -> As free

        // Commit NEXT tile's features into As (so GEMM1 can start right after
        // the next barrier, concurrent with this tile's epi2)
        if (nxt < NTILES) {
            #pragma unroll
            for (int j = 0; j < 8; j++) {
                __half2 lo = __floats2half2_rn(pf[j].x, pf[j].y);
                __half2 hi = __floats2half2_rn(pf[j].z, pf[j].w);
                uint2 pk; pk.x = *(uint32_t*)&lo; pk.y = *(uint32_t*)&hi;
                *(uint2*)(As + g*A_STRIDE + j*16 + cc) = pk;
            }
        }
        __syncthreads();   // next feat ready

        // Epilogue2: tanh(.+b2) (MUFU), fused W_out dot, shfl + shared-atomic
        // reduce. NO barrier after: warps flow straight into next GEMM1.
        #pragma unroll
        for (int mt = 0; mt < 2; mt++) {
            float p0 = 0.f, p1 = 0.f;
            #pragma unroll
            for (int nt = 0; nt < 4; nt++) {
                int col = nb + nt*8 + 2*cq;
                float w0 = wouts[col], w1 = wouts[col+1];
                float bb0 = b2s[col], bb1 = b2s[col+1];
                p0 += fast_tanh(acc[mt][nt][0] + bb0) * w0
                    + fast_tanh(acc[mt][nt][1] + bb1) * w1;
                p1 += fast_tanh(acc[mt][nt][2] + bb0) * w0
                    + fast_tanh(acc[mt][nt][3] + bb1) * w1;
            }
            p0 += __shfl_xor_sync(0xffffffffu, p0, 1);
            p0 += __shfl_xor_sync(0xffffffffu, p0, 2);
            p1 += __shfl_xor_sync(0xffffffffu, p1, 1);
            p1 += __shfl_xor_sync(0xffffffffu, p1, 2);
            if (cq == 0) {
                int r = mb + mt*16 + gid;
                atomicAdd(&yts[r],     p0);
                atomicAdd(&yts[r + 8], p1);
            }
        }

        prev_t = t; prev_g0 = g0;
    }

    // Drain: store the last tile's output
    __syncthreads();
    if (prev_t >= 0 && tid < 128)
        out[(size_t)prev_t * NGRID + prev_g0 + tid] = yts[tid] + bout;
}

extern "C" void kernel_launch(void* const* d_in, const int* in_sizes, int n_in,
                              void* d_out, int out_size) {
    const float* x     = (const float*)d_in[0];
    const float* W_in  = (const float*)d_in[1];
    const float* b_in  = (const float*)d_in[2];
    const float* W_ih  = (const float*)d_in[3];
    const float* b_ih  = (const float*)d_in[4];
    /* d_in[5] = W_hh — dead in the reference (only b_hh is used) */
    const float* b_hh  = (const float*)d_in[6];
    const float* W_out = (const float*)d_in[7];
    const float* b_out = (const float*)d_in[8];
    float* out = (float*)d_out;

    cudaFuncSetAttribute(narx_main, cudaFuncAttributeMaxDynamicSharedMemorySize, SMEM_BYTES);
    int dev = 0, sms = 0;
    cudaGetDevice(&dev);
    cudaDeviceGetAttribute(&sms, cudaDevAttrMultiProcessorCount, dev);
    if (sms <= 0) sms = 148;

    narx_main<<<sms, NTHREADS, SMEM_BYTES>>>(x, W_in, b_in, W_ih, b_ih, b_hh,
                                             W_out, b_out, out);
}

// round 15
// speedup vs baseline: 2.1317x; 1.2031x over previous
#include <cuda_runtime.h>
#include <cuda_fp16.h>
#include <cstdint>
#include <cstddef>

// Problem constants (fixed by the reference)
#define NTT    1024
#define NGRID  2048
#define MAXD   8
#define TROWS  (NTT - MAXD)          // 1016 computed time rows
#define NTILES (TROWS * (NGRID/128)) // 16256 tiles of 128 g-rows

#define NTHREADS 512                 // 16 warps = 4 groups of 4 warps

// fp16 SMEM strides in __half units. Row = 128 halves data + 8 pad = 136.
// Word index = row*68 + k/2; 68 mod 32 = 4 -> ldmatrix 8-row phases hit
// word-groups 4r mod 32 = all 32 banks exactly once -> conflict-free.
#define A_STRIDE 136
#define W_STRIDE 136
#define ROW_BYTES (A_STRIDE*2)       // 272
// Layout: W1 | W2 | A (each 128*136 halves) then fp32 b1,b2,wout,yts
#define SMEM_HALVES (3*128*136)
#define SMEM_BYTES  (SMEM_HALVES*2 + 4*128*4)   // 104,448 + 2,048 = 106,496 B

// Named barrier per 4-warp row-group (ids 1..4; 0 reserved for __syncthreads)
#define BAR_GROUP(id) asm volatile("bar.sync %0, 128;" :: "r"(id) : "memory")

// tanh(x) = 1 - 2/(exp(2x)+1) via MUFU ex2 + MUFU rcp (~1e-7 rel err)
__device__ __forceinline__ float fast_tanh(float x) {
    float e;
    asm("ex2.approx.f32 %0, %1;" : "=f"(e) : "f"(x * 2.885390081777927f)); // 2*log2(e)
    float r;
    asm("rcp.approx.f32 %0, %1;" : "=f"(r) : "f"(e + 1.0f));
    return fmaf(-2.0f, r, 1.0f);
}

// m16n8k16 fp16 MMA, fp32 accumulate
__device__ __forceinline__ void mma_f16(float d[4],
                                        uint32_t a0, uint32_t a1, uint32_t a2, uint32_t a3,
                                        uint32_t b0, uint32_t b1) {
    asm volatile(
        "mma.sync.aligned.m16n8k16.row.col.f32.f16.f16.f32 "
        "{%0,%1,%2,%3}, {%4,%5,%6,%7}, {%8,%9}, {%0,%1,%2,%3};"
        : "+f"(d[0]), "+f"(d[1]), "+f"(d[2]), "+f"(d[3])
        : "r"(a0), "r"(a1), "r"(a2), "r"(a3), "r"(b0), "r"(b1));
}

// ldmatrix x4: one instruction loads 4 8x8 fp16 matrices
__device__ __forceinline__ void ldsm4(uint32_t r[4], uint32_t addr) {
    asm volatile("ldmatrix.sync.aligned.m8n8.x4.shared.b16 {%0,%1,%2,%3}, [%4];"
        : "=r"(r[0]), "=r"(r[1]), "=r"(r[2]), "=r"(r[3]) : "r"(addr));
}

__device__ __forceinline__ uint32_t smem_u32(const void* p) {
    uint32_t a;
    asm("{ .reg .u64 t; cvta.to.shared.u64 t, %1; cvt.u32.u64 %0, t; }"
        : "=r"(a) : "l"(p));
    return a;
}

// ---------------------------------------------------------------------------
// 32x32 warp sub-tile of a (32-row slab) x 128 x 128 fp16 GEMM via ldmatrix.
// Per thread (p = lane&7, sel = lane>>3):
//   Aaddr: matrix sel -> rows mb + (sel&1)*8 + p, k-offset (sel>>1)*8 halves
//   Baddr: matrix sel -> rows nb + sel*8 + p  => r[sel] = b0[nt=sel]; +16B = b1
// 3 LDSM.x4 + 8 HMMA per K-step.
// ---------------------------------------------------------------------------
__device__ __forceinline__ void gemm_tile(uint32_t Aaddr, uint32_t Baddr,
                                          float acc[2][4][4]) {
    #pragma unroll
    for (int ks = 0; ks < 8; ks++) {
        uint32_t a0[4], b0[4], b1[4];
        ldsm4(b0, Baddr + ks*32);
        ldsm4(b1, Baddr + ks*32 + 16);
        ldsm4(a0, Aaddr + ks*32);
        #pragma unroll
        for (int nt = 0; nt < 4; nt++) {
            mma_f16(acc[0][nt], a0[0], a0[1], a0[2], a0[3], b0[nt], b1[nt]);
        }
        uint32_t a1[4];
        ldsm4(a1, Aaddr + 16*ROW_BYTES + ks*32);   // rows +16
        #pragma unroll
        for (int nt = 0; nt < 4; nt++) {
            mma_f16(acc[1][nt], a1[0], a1[1], a1[2], a1[3], b0[nt], b1[nt]);
        }
    }
}

// Group-local feature prefetch: 32-row slab (rows mb..mb+31 of the tile),
// 8 LDG.128 per thread (128 threads x 1 float4 per delay slab of 2KB).
__device__ __forceinline__ void load_feat(const float* __restrict__ x, int t,
                                          int gbase, int wtid, float4 pf[8]) {
    #pragma unroll
    for (int j = 0; j < 8; j++)
        pf[j] = *(const float4*)(
            x + ((size_t)(t - 1 - j) * NGRID + gbase) * 16 + (size_t)wtid * 4);
}

// ---------------------------------------------------------------------------
// SINGLE persistent kernel, 512 threads = 4 INDEPENDENT 4-warp pipelines.
// As rows are partitioned by row-group (group wr owns rows mb..mb+31 for feat,
// GEMM1 reads, epi1 writes, GEMM2 reads, yts and output slab); groups share
// only read-only weights, so ALL in-loop barriers are 128-thread named
// barriers. Groups drift in phase -> one group's MUFU/LDS overlaps another's
// HMMA, breaking the whole-CTA phase lock that capped tensor at ~38%.
// ---------------------------------------------------------------------------
__global__ __launch_bounds__(NTHREADS, 1)
void narx_main(const float* __restrict__ x,
               const float* __restrict__ W_in,  const float* __restrict__ b_in,
               const float* __restrict__ W_ih,  const float* __restrict__ b_ih,
               const float* __restrict__ b_hh,  const float* __restrict__ W_out,
               const float* __restrict__ b_out, float* __restrict__ out) {
    extern __shared__ __half smh[];
    __half* W1s = smh;                      // [h=128][k] stride W_STRIDE (folded W_in)
    __half* W2s = W1s + 128*W_STRIDE;       // [h=128][k] = W_ih (row-major [n][k])
    __half* As  = W2s + 128*W_STRIDE;       // [row=128][k] feat / h_in tile
    float* b1s   = (float*)(smh + SMEM_HALVES);
    float* b2s   = b1s + 128;
    float* wouts = b2s + 128;
    float* yts   = wouts + 128;

    const int tid  = threadIdx.x;
    const int warp = tid >> 5;
    const int lane = tid & 31;
    const int gid  = lane >> 2;   // group id 0..7 (within warp)
    const int cq   = lane & 3;    // quad 0..3
    const int wr   = warp >> 2;          // row group 0..3
    const int mb   = wr * 32;            // row slab base: 0,32,64,96
    const int nb   = (warp & 3) * 32;    // col base: 0,32,64,96
    const int wtid = tid & 127;          // thread index within group
    const int barid = 1 + wr;            // named barrier id

    // ldmatrix per-thread address bases
    const int p   = lane & 7;
    const int sel = lane >> 3;
    const uint32_t W1b = smem_u32(W1s), W2b = smem_u32(W2s), Asb = smem_u32(As);
    const uint32_t Aaddr  = Asb + (uint32_t)(mb + (sel & 1)*8 + p) * ROW_BYTES
                                + (uint32_t)(sel >> 1) * 16;
    const uint32_t B1addr = W1b + (uint32_t)(nb + sel*8 + p) * ROW_BYTES;
    const uint32_t B2addr = W2b + (uint32_t)(nb + sel*8 + p) * ROW_BYTES;

    // ---- head passthrough: out[0:8, :, 0] = x[0:8, :, 15] (striped) ----
    for (int i = blockIdx.x * NTHREADS + tid; i < MAXD * NGRID; i += gridDim.x * NTHREADS)
        out[i] = x[(size_t)i * 16 + 15];

    // ---- per-CTA prep: fold W_in (128x144, dup offset -1) into W1s[h][k],
    //      copy W_ih into W2s[h][k]; fp16-round. L2-broadcast reads. ----
    for (int i = tid; i < 128*128; i += NTHREADS) {
        int h = i >> 7, k = i & 127;
        int d = (k >> 4) + 1;   // delay 1..8
        int c = k & 15;         // channel 0..15 (15 == yf channel)
        int j = 9 - d;          // 1..8
        float v;
        if (c < 15) {
            v = W_in[h*144 + j*15 + c];
            if (d == 1) v += W_in[h*144 + c];          // duplicate offset -1 (j=0)
        } else {
            v = W_in[h*144 + 135 + j];
            if (d == 1) v += W_in[h*144 + 135];
        }
        W1s[h*W_STRIDE + k] = __float2half_rn(v);
        W2s[h*W_STRIDE + k] = __float2half_rn(W_ih[h*128 + k]);
    }
    if (tid < 128) {
        b1s[tid]   = b_in[tid];
        b2s[tid]   = b_ih[tid] + b_hh[tid];
        wouts[tid] = W_out[tid];
        yts[tid]   = 0.f;
    }

    const float bout = b_out[0];
    // group-local feat-commit coordinates: row mb+gl, channel block cc
    const int gl = wtid >> 2;        // 0..31 local row
    const int cc = (wtid & 3) * 4;   // 0,4,8,12
    __half* Acommit = As + (mb + gl) * A_STRIDE + cc;

    // Prologue: load + commit first tile's feature slab (group-local rows)
    int tile = blockIdx.x;
    float4 pf[8];
    if (tile < NTILES) {
        load_feat(x, MAXD + (tile >> 4), (tile & 15) * 128 + mb, wtid, pf);
        #pragma unroll
        for (int j = 0; j < 8; j++) {
            __half2 lo = __floats2half2_rn(pf[j].x, pf[j].y);
            __half2 hi = __floats2half2_rn(pf[j].z, pf[j].w);
            uint2 pk; pk.x = *(uint32_t*)&lo; pk.y = *(uint32_t*)&hi;
            *(uint2*)(Acommit + j*16) = pk;
        }
    }
    __syncthreads();   // feat0 + weights + yts ready (only CTA-wide sync)

    int prev_t = -1, prev_g0 = 0;

    for (; tile < NTILES; tile += gridDim.x) {
        const int t  = MAXD + (tile >> 4);
        const int g0 = (tile & 15) * 128;

        // Prefetch next tile's feature slab (consumed at end of iteration)
        const int nxt = tile + gridDim.x;
        if (nxt < NTILES)
            load_feat(x, MAXD + (nxt >> 4), (nxt & 15) * 128 + mb, wtid, pf);

        // ---- GEMM1: h_pre_in = feat @ Wc^T  (overlaps prev tile's epi2) ----
        float acc[2][4][4];
        #pragma unroll
        for (int mt = 0; mt < 2; mt++)
            #pragma unroll
            for (int nt = 0; nt < 4; nt++)
                #pragma unroll
                for (int q = 0; q < 4; q++) acc[mt][nt][q] = 0.f;

        gemm_tile(Aaddr, B1addr, acc);
        BAR_GROUP(barid);  // slab feat reads done; group's epi2 atomics visible

        // Deferred output store for previous tile (group slab), re-zero yts
        if (wtid < 32) {
            if (prev_t >= 0)
                out[(size_t)prev_t * NGRID + prev_g0 + mb + wtid] = yts[mb + wtid] + bout;
            yts[mb + wtid] = 0.f;
        }

        // Epilogue1: relu(.+b_in) -> fp16, write h_in back into slab rows.
        #pragma unroll
        for (int mt = 0; mt < 2; mt++) {
            int r = mb + mt*16 + gid;
            #pragma unroll
            for (int nt = 0; nt < 4; nt++) {
                int col = nb + nt*8 + 2*cq;
                float bb0 = b1s[col], bb1 = b1s[col+1];
                __half2 v0 = __floats2half2_rn(fmaxf(acc[mt][nt][0] + bb0, 0.f),
                                               fmaxf(acc[mt][nt][1] + bb1, 0.f));
                __half2 v1 = __floats2half2_rn(fmaxf(acc[mt][nt][2] + bb0, 0.f),
                                               fmaxf(acc[mt][nt][3] + bb1, 0.f));
                *(__half2*)(As + (size_t)r*A_STRIDE + col)     = v0;
                *(__half2*)(As + (size_t)(r+8)*A_STRIDE + col) = v1;
            }
        }
        BAR_GROUP(barid);  // slab h_in ready (written by this group's 4 warps)

        // ---- GEMM2: h_pre = h_in @ W_ih^T ----
        #pragma unroll
        for (int mt = 0; mt < 2; mt++)
            #pragma unroll
            for (int nt = 0; nt < 4; nt++)
                #pragma unroll
                for (int q = 0; q < 4; q++) acc[mt][nt][q] = 0.f;

        gemm_tile(Aaddr, B2addr, acc);
        BAR_GROUP(barid);  // slab h_in reads done -> slab rows free

        // Commit NEXT tile's feature slab (so next GEMM1 starts right after
        // the group barrier, concurrent with this tile's epi2)
        if (nxt < NTILES) {
            #pragma unroll
            for (int j = 0; j < 8; j++) {
                __half2 lo = __floats2half2_rn(pf[j].x, pf[j].y);
                __half2 hi = __floats2half2_rn(pf[j].z, pf[j].w);
                uint2 pk; pk.x = *(uint32_t*)&lo; pk.y = *(uint32_t*)&hi;
                *(uint2*)(Acommit + j*16) = pk;
            }
        }
        BAR_GROUP(barid);  // next feat slab ready

        // Epilogue2: tanh(.+b2) (MUFU), fused W_out dot, shfl + shared-atomic
        // reduce into group's yts rows. NO barrier after: flow into next GEMM1.
        #pragma unroll
        for (int mt = 0; mt < 2; mt++) {
            float p0 = 0.f, p1 = 0.f;
            #pragma unroll
            for (int nt = 0; nt < 4; nt++) {
                int col = nb + nt*8 + 2*cq;
                float w0 = wouts[col], w1 = wouts[col+1];
                float bb0 = b2s[col], bb1 = b2s[col+1];
                p0 += fast_tanh(acc[mt][nt][0] + bb0) * w0
                    + fast_tanh(acc[mt][nt][1] + bb1) * w1;
                p1 += fast_tanh(acc[mt][nt][2] + bb0) * w0
                    + fast_tanh(acc[mt][nt][3] + bb1) * w1;
            }
            p0 += __shfl_xor_sync(0xffffffffu, p0, 1);
            p0 += __shfl_xor_sync(0xffffffffu, p0, 2);
            p1 += __shfl_xor_sync(0xffffffffu, p1, 1);
            p1 += __shfl_xor_sync(0xffffffffu, p1, 2);
            if (cq == 0) {
                int r = mb + mt*16 + gid;
                atomicAdd(&yts[r],     p0);
                atomicAdd(&yts[r + 8], p1);
            }
        }

        prev_t = t; prev_g0 = g0;
    }

    // Drain: store the last tile's output slab
    BAR_GROUP(barid);
    if (prev_t >= 0 && wtid < 32)
        out[(size_t)prev_t * NGRID + prev_g0 + mb + wtid] = yts[mb + wtid] + bout;
}

extern "C" void kernel_launch(void* const* d_in, const int* in_sizes, int n_in,
                              void* d_out, int out_size) {
    const float* x     = (const float*)d_in[0];
    const float* W_in  = (const float*)d_in[1];
    const float* b_in  = (const float*)d_in[2];
    const float* W_ih  = (const float*)d_in[3];
    const float* b_ih  = (const float*)d_in[4];
    /* d_in[5] = W_hh — dead in the reference (only b_hh is used) */
    const float* b_hh  = (const float*)d_in[6];
    const float* W_out = (const float*)d_in[7];
    const float* b_out = (const float*)d_in[8];
    float* out = (float*)d_out;

    cudaFuncSetAttribute(narx_main, cudaFuncAttributeMaxDynamicSharedMemorySize, SMEM_BYTES);
    int dev = 0, sms = 0;
    cudaGetDevice(&dev);
    cudaDeviceGetAttribute(&sms, cudaDevAttrMultiProcessorCount, dev);
    if (sms <= 0) sms = 148;

    narx_main<<<sms, NTHREADS, SMEM_BYTES>>>(x, W_in, b_in, W_ih, b_ih, b_hh,
                                             W_out, b_out, out);
}